// round 9
// baseline (speedup 1.0000x reference)
#include <cuda_runtime.h>
#include <cuda_bf16.h>
#include <stdint.h>
#include <math.h>

#define BB 4
#define TT 1024
#define CC 1024
#define HH 16
#define HD 64
#define NEL (BB*TT*CC)          // 4194304
#define NW  (CC*CC)             // 1048576

// ---------------- scratch (device globals: allocation-free) ----------------
__device__ __nv_bfloat16 g_inh[3][NEL], g_inl[3][NEL];   // split query,key,value (row-major)
__device__ __nv_bfloat16 g_Wh[4][NW],  g_Wl[4][NW];      // split Wq,Wk,Wv,Wo (row-major)
__device__ unsigned g_qfh[NEL/2], g_qfl[NEL/2];          // proj q (x8) bf16 A-frags
__device__ unsigned g_kfh[NEL/2], g_kfl[NEL/2];          // proj k bf16 B-frags
__device__ unsigned g_vtf[NEL];                          // proj v tf32 B-frags
__device__ unsigned g_qrf[NEL];                          // raw q x8 tf32 A-frags
__device__ unsigned g_rtf[32*4096];                      // relpad tf32 B-frag tiles
__device__ __nv_bfloat16 g_ctxh[NEL], g_ctxl[NEL];       // attention out, split row-major

// ---------------- helpers ----------------
__device__ __forceinline__ unsigned f2tf32(float x) {
    unsigned u;
    asm("cvt.rna.tf32.f32 %0, %1;" : "=r"(u) : "f"(x));
    return u;
}
__device__ __forceinline__ void mma_tf32(float4& c, const uint4& a, const uint2& b) {
    asm volatile(
        "mma.sync.aligned.m16n8k8.row.col.f32.tf32.tf32.f32 "
        "{%0,%1,%2,%3}, {%4,%5,%6,%7}, {%8,%9}, {%0,%1,%2,%3};"
        : "+f"(c.x), "+f"(c.y), "+f"(c.z), "+f"(c.w)
        : "r"(a.x), "r"(a.y), "r"(a.z), "r"(a.w), "r"(b.x), "r"(b.y));
}
__device__ __forceinline__ void mma_bf16(float4& c, const uint4& a, const uint2& b) {
    asm volatile(
        "mma.sync.aligned.m16n8k16.row.col.f32.bf16.bf16.f32 "
        "{%0,%1,%2,%3}, {%4,%5,%6,%7}, {%8,%9}, {%0,%1,%2,%3};"
        : "+f"(c.x), "+f"(c.y), "+f"(c.z), "+f"(c.w)
        : "r"(a.x), "r"(a.y), "r"(a.z), "r"(a.w), "r"(b.x), "r"(b.y));
}
__device__ __forceinline__ void split_pair(float x, float y, unsigned& hi, unsigned& lo) {
    __nv_bfloat16 hx = __float2bfloat16(x), hy = __float2bfloat16(y);
    __nv_bfloat162 H; H.x = hx; H.y = hy;
    __nv_bfloat162 L;
    L.x = __float2bfloat16(x - __bfloat162float(hx));
    L.y = __float2bfloat16(y - __bfloat162float(hy));
    hi = *reinterpret_cast<unsigned*>(&H);
    lo = *reinterpret_cast<unsigned*>(&L);
}

// ---------------- convert A: split q/k/v row-major + qraw tf32 A-frags ----------------
__global__ void convA(const float* __restrict__ q, const float* __restrict__ k,
                      const float* __restrict__ v,
                      __nv_bfloat16* __restrict__ inh, __nv_bfloat16* __restrict__ inl,
                      unsigned* __restrict__ qrf)
{
    int blk = blockIdx.x;
    int arr = blk >> 12;
    int i = ((blk & 4095) << 8) + threadIdx.x;
    const float* src = arr == 0 ? q : (arr == 1 ? k : v);
    float4 v4 = ((const float4*)src)[i];
    unsigned h0, l0, h1, l1;
    split_pair(v4.x, v4.y, h0, l0);
    split_pair(v4.z, v4.w, h1, l1);
    ((uint2*)(inh + (size_t)arr * NEL))[i] = make_uint2(h0, h1);
    ((uint2*)(inl + (size_t)arr * NEL))[i] = make_uint2(l0, l1);
    if (arr == 0) {
        int e = i * 4;
        int m = e >> 10, ch = e & 1023;
        int hh_ = ch >> 6, d = ch & 63;
        int b_ = m >> 10, tt = (m >> 7) & 7, mr = m & 127;
        size_t blko = ((size_t)((b_ * 8 + tt) * 16 + hh_)) << 13;
        int base = ((d >> 3) * 8 + (mr >> 4)) * 128 + (mr & 7) * 16
                 + ((mr >> 3) & 1) + 2 * ((d >> 2) & 1);
        qrf[blko + base +  0] = f2tf32(8.f * v4.x);
        qrf[blko + base +  4] = f2tf32(8.f * v4.y);
        qrf[blko + base +  8] = f2tf32(8.f * v4.z);
        qrf[blko + base + 12] = f2tf32(8.f * v4.w);
    }
}

// ---------------- convert W: split 4 weights + relpad tf32 B-frag tiles ----------------
__global__ void convW(const float* __restrict__ Wq, const float* __restrict__ Wk,
                      const float* __restrict__ Wv, const float* __restrict__ Wo,
                      const float* __restrict__ rel_emb,
                      __nv_bfloat16* __restrict__ Wh, __nv_bfloat16* __restrict__ Wl,
                      unsigned* __restrict__ rtf)
{
    int blk = blockIdx.x;
    if (blk < 4096) {
        int arr = blk >> 10;
        int i = ((blk & 1023) << 8) + threadIdx.x;
        const float* src = arr == 0 ? Wq : (arr == 1 ? Wk : (arr == 2 ? Wv : Wo));
        float4 v4 = ((const float4*)src)[i];
        unsigned h0, l0, h1, l1;
        split_pair(v4.x, v4.y, h0, l0);
        split_pair(v4.z, v4.w, h1, l1);
        ((uint2*)(Wh + (size_t)arr * NW))[i] = make_uint2(h0, h1);
        ((uint2*)(Wl + (size_t)arr * NW))[i] = make_uint2(l0, l1);
    } else {
        int e = ((blk - 4096) << 8) + threadIdx.x;
        int tt = e >> 12, rem = e & 4095;
        int ul = rem >> 6, d = rem & 63;
        int u = tt * 64 + ul;
        int src = u - 24;
        src = src < 0 ? 0 : (src > 1998 ? 1998 : src);
        int addr = tt * 4096 + ((d >> 3) * 8 + (ul >> 3)) * 64
                 + ((ul & 7) * 4 + (d & 3)) * 2 + ((d >> 2) & 1);
        rtf[addr] = f2tf32(rel_emb[src * HD + d]);
    }
}

// ---------------- per-element epilogue store (round-6-validated layouts) ----------------
template <int MODE>
__device__ __forceinline__ void epi_store(int m0, int n0, float x0, float x1,
                                          void* o0, void* o1, int N)
{
    if (MODE == 0) {
        *(float2*)((float*)o0 + (size_t)m0 * N + n0) = make_float2(x0, x1);
    } else {
        int b_ = m0 >> 10, hh_ = n0 >> 6, d = n0 & 63;
        if (MODE == 1) {
            int tt = (m0 >> 7) & 7, mr = m0 & 127;
            size_t blk = ((size_t)((b_ * 8 + tt) * 16 + hh_)) << 12;
            int addr = ((d >> 4) * 8 + (mr >> 4)) * 128
                     + ((mr & 7) * 4 + ((d >> 1) & 3)) * 4
                     + ((mr >> 3) & 1) + 2 * ((d >> 3) & 1);
            unsigned hw, lw;
            split_pair(x0, x1, hw, lw);
            ((unsigned*)o0)[blk + addr] = hw; ((unsigned*)o1)[blk + addr] = lw;
        } else if (MODE == 2) {
            int stt = (m0 >> 6) & 15, sr = m0 & 63;
            size_t blk = ((size_t)((b_ * 16 + stt) * 16 + hh_)) << 11;
            int addr = ((d >> 4) * 8 + (sr >> 3)) * 64
                     + ((sr & 7) * 4 + ((d >> 1) & 3)) * 2 + ((d >> 3) & 1);
            unsigned hw, lw;
            split_pair(x0, x1, hw, lw);
            ((unsigned*)o0)[blk + addr] = hw; ((unsigned*)o1)[blk + addr] = lw;
        } else {
            int stt = (m0 >> 6) & 15, sr = m0 & 63;
            size_t blk = ((size_t)((b_ * 16 + stt) * 16 + hh_)) << 12;
            int a00 = ((sr >> 3) * 8 + (d >> 3)) * 64
                    + ((d & 7) * 4 + (sr & 3)) * 2 + ((sr >> 2) & 1);
            ((unsigned*)o0)[blk + a00]     = f2tf32(x0);
            ((unsigned*)o0)[blk + a00 + 8] = f2tf32(x1);
        }
    }
}

// ========== bf16 3-term NT GEMM, block 128x256, warp tile 64x64 ==========
// 8 warps (2 m-rows x 4 n-cols). Smem in exact mma fragment order, double-buffered.
// A frags: [stage][mtile(8)][lane(32)][4]; B frags: [stage][ntile(32)][lane(32)][2].
#define GEMM_SMEM 49152

template <int MODE>
__global__ __launch_bounds__(256)
void gemm3(const __nv_bfloat16* __restrict__ Ah, const __nv_bfloat16* __restrict__ Al,
           const __nv_bfloat16* __restrict__ Bh, const __nv_bfloat16* __restrict__ Bl,
           const float* __restrict__ bias, void* __restrict__ o0, void* __restrict__ o1,
           int M, int N, int K, float scale)
{
    extern __shared__ unsigned smg[];
    unsigned* As_h = smg;            // [2][1024]
    unsigned* As_l = smg + 2048;
    unsigned* Bs_h = smg + 4096;     // [2][2048]
    unsigned* Bs_l = smg + 8192;

    const int tid = threadIdx.x;
    const int lane = tid & 31;
    const int warp = tid >> 5;
    const int wrow = warp & 1, wcol = warp >> 1;
    const int bm = blockIdx.y * 128, bn = blockIdx.x * 256;
    const int r2 = tid >> 1, c2 = tid & 1;   // A row / k-half; B rows r2 and r2+128

    float4 acc[4][8];
#pragma unroll
    for (int i = 0; i < 4; i++)
#pragma unroll
        for (int j = 0; j < 8; j++) acc[i][j] = make_float4(0.f, 0.f, 0.f, 0.f);

    uint4 sah, sal, sbh0, sbl0, sbh1, sbl1;
    sah  = *(const uint4*)(Ah + (size_t)(bm + r2) * K + c2 * 8);
    sal  = *(const uint4*)(Al + (size_t)(bm + r2) * K + c2 * 8);
    sbh0 = *(const uint4*)(Bh + (size_t)(bn + r2) * K + c2 * 8);
    sbl0 = *(const uint4*)(Bl + (size_t)(bn + r2) * K + c2 * 8);
    sbh1 = *(const uint4*)(Bh + (size_t)(bn + r2 + 128) * K + c2 * 8);
    sbl1 = *(const uint4*)(Bl + (size_t)(bn + r2 + 128) * K + c2 * 8);

    for (int kb = 0; kb < K; kb += 16) {
        const int st = (kb >> 4) & 1;
        {
            unsigned awh[4] = {sah.x, sah.y, sah.z, sah.w};
            unsigned awl[4] = {sal.x, sal.y, sal.z, sal.w};
            unsigned bh0[4] = {sbh0.x, sbh0.y, sbh0.z, sbh0.w};
            unsigned bl0[4] = {sbl0.x, sbl0.y, sbl0.z, sbl0.w};
            unsigned bh1[4] = {sbh1.x, sbh1.y, sbh1.z, sbh1.w};
            unsigned bl1[4] = {sbl1.x, sbl1.y, sbl1.z, sbl1.w};
#pragma unroll
            for (int p = 0; p < 4; p++) {
                int aaddr = st * 1024 + (r2 >> 4) * 128 + ((r2 & 7) * 4 + p) * 4
                          + ((r2 >> 3) & 1) + 2 * c2;
                As_h[aaddr] = awh[p];
                As_l[aaddr] = awl[p];
                int b0 = st * 2048 + (r2 >> 3) * 64 + ((r2 & 7) * 4 + p) * 2 + c2;
                Bs_h[b0] = bh0[p];
                Bs_l[b0] = bl0[p];
                int b1 = st * 2048 + ((r2 + 128) >> 3) * 64 + ((r2 & 7) * 4 + p) * 2 + c2;
                Bs_h[b1] = bh1[p];
                Bs_l[b1] = bl1[p];
            }
        }
        __syncthreads();

        if (kb + 16 < K) {
            sah  = *(const uint4*)(Ah + (size_t)(bm + r2) * K + kb + 16 + c2 * 8);
            sal  = *(const uint4*)(Al + (size_t)(bm + r2) * K + kb + 16 + c2 * 8);
            sbh0 = *(const uint4*)(Bh + (size_t)(bn + r2) * K + kb + 16 + c2 * 8);
            sbl0 = *(const uint4*)(Bl + (size_t)(bn + r2) * K + kb + 16 + c2 * 8);
            sbh1 = *(const uint4*)(Bh + (size_t)(bn + r2 + 128) * K + kb + 16 + c2 * 8);
            sbl1 = *(const uint4*)(Bl + (size_t)(bn + r2 + 128) * K + kb + 16 + c2 * 8);
        }

        uint4 ah[4], al[4];
#pragma unroll
        for (int i = 0; i < 4; i++) {
            ah[i] = *(const uint4*)&As_h[st * 1024 + (wrow * 4 + i) * 128 + lane * 4];
            al[i] = *(const uint4*)&As_l[st * 1024 + (wrow * 4 + i) * 128 + lane * 4];
        }
#pragma unroll
        for (int j = 0; j < 8; j++) {
            uint2 bh = *(const uint2*)&Bs_h[st * 2048 + (wcol * 8 + j) * 64 + lane * 2];
            uint2 bl = *(const uint2*)&Bs_l[st * 2048 + (wcol * 8 + j) * 64 + lane * 2];
#pragma unroll
            for (int i = 0; i < 4; i++) {
                mma_bf16(acc[i][j], ah[i], bl);
                mma_bf16(acc[i][j], al[i], bh);
                mma_bf16(acc[i][j], ah[i], bh);
            }
        }
        __syncthreads();
    }

    const int g = lane >> 2, tig = lane & 3;
#pragma unroll
    for (int i = 0; i < 4; i++) {
#pragma unroll
        for (int j = 0; j < 8; j++) {
            int m0 = bm + wrow * 64 + i * 16 + g;
            int n0 = bn + wcol * 64 + j * 8 + tig * 2;
            float b0 = __ldg(bias + n0), b1 = __ldg(bias + n0 + 1);
            float x0 = (acc[i][j].x + b0) * scale, x1 = (acc[i][j].y + b1) * scale;
            float x2 = (acc[i][j].z + b0) * scale, x3 = (acc[i][j].w + b1) * scale;
            epi_store<MODE>(m0,     n0, x0, x1, o0, o1, N);
            epi_store<MODE>(m0 + 8, n0, x2, x3, o0, o1, N);
        }
    }
}

// ============== flash attention (unchanged from round 6) ==============
#define ZP2 66
#define FLASH3_WORDS (4096+4096+8192+2048+2048+4096+12288+8192+128*ZP2)
#define FLASH3_SMEM (FLASH3_WORDS * 4)

__global__ __launch_bounds__(256)
void flash_mma3(const unsigned* __restrict__ qfh, const unsigned* __restrict__ qfl,
                const unsigned* __restrict__ qrg,
                const unsigned* __restrict__ kfh, const unsigned* __restrict__ kfl,
                const unsigned* __restrict__ vtf, const unsigned* __restrict__ rtf,
                __nv_bfloat16* __restrict__ ctxh, __nv_bfloat16* __restrict__ ctxl)
{
    extern __shared__ unsigned smu[];
    unsigned* qf_h = smu;
    unsigned* qf_l = qf_h + 4096;
    unsigned* qrf  = qf_l + 4096;
    unsigned* kf_h = qrf + 8192;
    unsigned* kf_l = kf_h + 2048;
    unsigned* vf   = kf_l + 2048;
    unsigned* rf   = vf + 4096;
    unsigned* pfs  = rf + 12288;
    float* Zs      = (float*)(pfs + 8192);

    const int tid = threadIdx.x;
    const int lane = tid & 31;
    const int w = tid >> 5;
    const int g = lane >> 2, tig = lane & 3;
    const int b = blockIdx.y >> 4, hq = blockIdx.y & 15;
    const int bx = blockIdx.x, t0 = bx * 128;
    unsigned* pf = pfs + w * 1024;
    const int m0 = w * 16 + g, m1 = m0 + 8;

    {
        size_t qblk = ((size_t)((b * 8 + bx) * 16 + hq));
        const uint4* qh4 = (const uint4*)(qfh + (qblk << 12));
        const uint4* ql4 = (const uint4*)(qfl + (qblk << 12));
        const uint4* qr4 = (const uint4*)(qrg + (qblk << 13));
#pragma unroll
        for (int x = 0; x < 4; x++) ((uint4*)qf_h)[tid + 256 * x] = qh4[tid + 256 * x];
#pragma unroll
        for (int x = 0; x < 4; x++) ((uint4*)qf_l)[tid + 256 * x] = ql4[tid + 256 * x];
#pragma unroll
        for (int x = 0; x < 8; x++) ((uint4*)qrf)[tid + 256 * x] = qr4[tid + 256 * x];
    }

    float m_i[2] = {-1e30f, -1e30f}, l_i[2] = {0.f, 0.f};
    float4 o[8];
#pragma unroll
    for (int j = 0; j < 8; j++) o[j] = make_float4(0.f, 0.f, 0.f, 0.f);

    for (int i = 0; i < 16; i++) {
        int T = i - 2 * bx + 14;
        __syncthreads();

        {
            size_t kb_ = (size_t)((b * 16 + i) * 16 + hq);
            const uint4* kh4 = (const uint4*)(kfh + (kb_ << 11));
            const uint4* kl4 = (const uint4*)(kfl + (kb_ << 11));
            const uint4* v4  = (const uint4*)(vtf + (kb_ << 12));
#pragma unroll
            for (int x = 0; x < 2; x++) ((uint4*)kf_h)[tid + 256 * x] = kh4[tid + 256 * x];
#pragma unroll
            for (int x = 0; x < 2; x++) ((uint4*)kf_l)[tid + 256 * x] = kl4[tid + 256 * x];
#pragma unroll
            for (int x = 0; x < 4; x++) ((uint4*)vf)[tid + 256 * x] = v4[tid + 256 * x];
            if (i == 0) {
#pragma unroll
                for (int it = 0; it < 2; it++) {
                    const uint4* rs = (const uint4*)(rtf + (size_t)(T + it) * 4096);
                    uint4* rd = (uint4*)(rf + ((T + it) % 3) * 4096);
#pragma unroll
                    for (int x = 0; x < 4; x++) rd[tid + 256 * x] = rs[tid + 256 * x];
                }
            }
            {
                const uint4* rs = (const uint4*)(rtf + (size_t)(T + 2) * 4096);
                uint4* rd = (uint4*)(rf + ((T + 2) % 3) * 4096);
#pragma unroll
                for (int x = 0; x < 4; x++) rd[tid + 256 * x] = rs[tid + 256 * x];
            }
        }
        __syncthreads();

        {
            const unsigned* rslot[3] = { rf + (T % 3) * 4096,
                                         rf + ((T + 1) % 3) * 4096,
                                         rf + ((T + 2) % 3) * 4096 };
            float4 zc[10];
#pragma unroll
            for (int j = 0; j < 10; j++) zc[j] = make_float4(0.f, 0.f, 0.f, 0.f);
#pragma unroll
            for (int ks = 0; ks < 8; ks++) {
                uint4 a = *(const uint4*)(qrf + (ks * 8 + w) * 128 + lane * 4);
#pragma unroll
                for (int j = 0; j < 10; j++) {
                    int nt = 14 - 2 * w + j;
                    uint2 bb = *(const uint2*)(rslot[nt >> 3] + (ks * 8 + (nt & 7)) * 64 + lane * 2);
                    mma_tf32(zc[j], a, bb);
                }
            }
#pragma unroll
            for (int j = 0; j < 10; j++) {
                int u = (14 - 2 * w + j) * 8 + 2 * tig;
                int s = u + m0 - 127;
                if ((unsigned)s < 64u)       Zs[m0 * ZP2 + s]     = zc[j].x;
                if ((unsigned)(s + 1) < 64u) Zs[m0 * ZP2 + s + 1] = zc[j].y;
                int s2 = s + 8;
                if ((unsigned)s2 < 64u)       Zs[m1 * ZP2 + s2]     = zc[j].z;
                if ((unsigned)(s2 + 1) < 64u) Zs[m1 * ZP2 + s2 + 1] = zc[j].w;
            }
        }
        __syncwarp();

        float4 sc[8];
#pragma unroll
        for (int j = 0; j < 8; j++) sc[j] = make_float4(0.f, 0.f, 0.f, 0.f);
#pragma unroll
        for (int kb = 0; kb < 4; kb++) {
            uint4 ah = *(const uint4*)(qf_h + (kb * 8 + w) * 128 + lane * 4);
            uint4 al = *(const uint4*)(qf_l + (kb * 8 + w) * 128 + lane * 4);
#pragma unroll
            for (int nt = 0; nt < 8; nt++) {
                uint2 bh = *(const uint2*)(kf_h + (kb * 8 + nt) * 64 + lane * 2);
                uint2 bl = *(const uint2*)(kf_l + (kb * 8 + nt) * 64 + lane * 2);
                mma_bf16(sc[nt], ah, bl);
                mma_bf16(sc[nt], al, bh);
                mma_bf16(sc[nt], ah, bh);
            }
        }

        float v0[16], v1[16];
#pragma unroll
        for (int nt = 0; nt < 8; nt++) {
            int s = nt * 8 + 2 * tig;
            v0[2*nt]   = sc[nt].x + Zs[m0 * ZP2 + s];
            v0[2*nt+1] = sc[nt].y + Zs[m0 * ZP2 + s + 1];
            v1[2*nt]   = sc[nt].z + Zs[m1 * ZP2 + s];
            v1[2*nt+1] = sc[nt].w + Zs[m1 * ZP2 + s + 1];
        }
        float lm0 = v0[0], lm1 = v1[0];
#pragma unroll
        for (int e = 1; e < 16; e++) { lm0 = fmaxf(lm0, v0[e]); lm1 = fmaxf(lm1, v1[e]); }
        lm0 = fmaxf(lm0, __shfl_xor_sync(~0u, lm0, 1));
        lm0 = fmaxf(lm0, __shfl_xor_sync(~0u, lm0, 2));
        lm1 = fmaxf(lm1, __shfl_xor_sync(~0u, lm1, 1));
        lm1 = fmaxf(lm1, __shfl_xor_sync(~0u, lm1, 2));
        float mn0 = fmaxf(m_i[0], lm0), mn1 = fmaxf(m_i[1], lm1);
        float al0 = __expf(m_i[0] - mn0), al1 = __expf(m_i[1] - mn1);
        m_i[0] = mn0; m_i[1] = mn1;
        float rs0 = 0.f, rs1 = 0.f;
#pragma unroll
        for (int nt = 0; nt < 8; nt++) {
            int s = nt * 8 + 2 * tig;
            float p00 = __expf(v0[2*nt]   - mn0);
            float p01 = __expf(v0[2*nt+1] - mn0);
            float p10 = __expf(v1[2*nt]   - mn1);
            float p11 = __expf(v1[2*nt+1] - mn1);
            rs0 += p00 + p01; rs1 += p10 + p11;
            int base = nt * 128 + (g * 4 + (s & 3)) * 4 + 2 * ((s >> 2) & 1);
            pf[base]     = f2tf32(p00);
            pf[base + 1] = f2tf32(p10);
            pf[base + 4] = f2tf32(p01);
            pf[base + 5] = f2tf32(p11);
        }
        rs0 += __shfl_xor_sync(~0u, rs0, 1); rs0 += __shfl_xor_sync(~0u, rs0, 2);
        rs1 += __shfl_xor_sync(~0u, rs1, 1); rs1 += __shfl_xor_sync(~0u, rs1, 2);
        l_i[0] = l_i[0] * al0 + rs0;
        l_i[1] = l_i[1] * al1 + rs1;
#pragma unroll
        for (int j = 0; j < 8; j++) {
            o[j].x *= al0; o[j].y *= al0; o[j].z *= al1; o[j].w *= al1;
        }
        __syncwarp();

#pragma unroll
        for (int ks = 0; ks < 8; ks++) {
            uint4 a = *(const uint4*)(pf + ks * 128 + lane * 4);
#pragma unroll
            for (int nt = 0; nt < 8; nt++) {
                uint2 bb = *(const uint2*)(vf + (ks * 8 + nt) * 64 + lane * 2);
                mma_tf32(o[nt], a, bb);
            }
        }
    }

    float inv0 = 1.f / l_i[0], inv1 = 1.f / l_i[1];
#pragma unroll
    for (int nt = 0; nt < 8; nt++) {
        int d = nt * 8 + 2 * tig;
        size_t i0 = (size_t)(b * TT + t0 + m0) * CC + hq * HD + d;
        size_t i1 = (size_t)(b * TT + t0 + m1) * CC + hq * HD + d;
        unsigned hh, ll;
        split_pair(o[nt].x * inv0, o[nt].y * inv0, hh, ll);
        ((unsigned*)ctxh)[i0 >> 1] = hh; ((unsigned*)ctxl)[i0 >> 1] = ll;
        split_pair(o[nt].z * inv1, o[nt].w * inv1, hh, ll);
        ((unsigned*)ctxh)[i1 >> 1] = hh; ((unsigned*)ctxl)[i1 >> 1] = ll;
    }
}

// ------------------------------ launch ------------------------------
extern "C" void kernel_launch(void* const* d_in, const int* in_sizes, int n_in,
                              void* d_out, int out_size)
{
    const float* query   = (const float*)d_in[0];
    const float* key     = (const float*)d_in[1];
    const float* value   = (const float*)d_in[2];
    const float* Wq      = (const float*)d_in[3];
    const float* bq      = (const float*)d_in[4];
    const float* Wk      = (const float*)d_in[5];
    const float* bk      = (const float*)d_in[6];
    const float* Wv      = (const float*)d_in[7];
    const float* bv      = (const float*)d_in[8];
    const float* Wo      = (const float*)d_in[9];
    const float* bo      = (const float*)d_in[10];
    const float* rel_emb = (const float*)d_in[11];
    float* out = (float*)d_out;

    __nv_bfloat16 *inh, *inl, *Wh, *Wl, *ctxh, *ctxl;
    unsigned *qfh, *qfl, *kfh, *kfl, *vtf, *qrf, *rtf;
    cudaGetSymbolAddress((void**)&inh, g_inh);
    cudaGetSymbolAddress((void**)&inl, g_inl);
    cudaGetSymbolAddress((void**)&Wh, g_Wh);
    cudaGetSymbolAddress((void**)&Wl, g_Wl);
    cudaGetSymbolAddress((void**)&qfh, g_qfh);
    cudaGetSymbolAddress((void**)&qfl, g_qfl);
    cudaGetSymbolAddress((void**)&kfh, g_kfh);
    cudaGetSymbolAddress((void**)&kfl, g_kfl);
    cudaGetSymbolAddress((void**)&vtf, g_vtf);
    cudaGetSymbolAddress((void**)&qrf, g_qrf);
    cudaGetSymbolAddress((void**)&rtf, g_rtf);
    cudaGetSymbolAddress((void**)&ctxh, g_ctxh);
    cudaGetSymbolAddress((void**)&ctxl, g_ctxl);

    convA<<<12288, 256>>>(query, key, value, inh, inl, qrf);
    convW<<<4608, 256>>>(Wq, Wk, Wv, Wo, rel_emb, Wh, Wl, rtf);

    cudaFuncSetAttribute(gemm3<0>, cudaFuncAttributeMaxDynamicSharedMemorySize, GEMM_SMEM);
    cudaFuncSetAttribute(gemm3<1>, cudaFuncAttributeMaxDynamicSharedMemorySize, GEMM_SMEM);
    cudaFuncSetAttribute(gemm3<2>, cudaFuncAttributeMaxDynamicSharedMemorySize, GEMM_SMEM);
    cudaFuncSetAttribute(gemm3<3>, cudaFuncAttributeMaxDynamicSharedMemorySize, GEMM_SMEM);

    dim3 gproj(CC / 256, (BB * TT) / 128);   // (4, 32) = 128 CTAs
    gemm3<1><<<gproj, 256, GEMM_SMEM>>>(inh + 0*(size_t)NEL, inl + 0*(size_t)NEL,
        Wh + 0*(size_t)NW, Wl + 0*(size_t)NW, bq, qfh, qfl, BB*TT, CC, CC, 8.0f);
    gemm3<2><<<gproj, 256, GEMM_SMEM>>>(inh + 1*(size_t)NEL, inl + 1*(size_t)NEL,
        Wh + 1*(size_t)NW, Wl + 1*(size_t)NW, bk, kfh, kfl, BB*TT, CC, CC, 1.0f);
    gemm3<3><<<gproj, 256, GEMM_SMEM>>>(inh + 2*(size_t)NEL, inl + 2*(size_t)NEL,
        Wh + 2*(size_t)NW, Wl + 2*(size_t)NW, bv, vtf, nullptr, BB*TT, CC, CC, 1.0f);

    cudaFuncSetAttribute(flash_mma3, cudaFuncAttributeMaxDynamicSharedMemorySize, FLASH3_SMEM);
    flash_mma3<<<dim3(TT / 128, BB * HH), 256, FLASH3_SMEM>>>(
        qfh, qfl, qrf, kfh, kfl, vtf, rtf, ctxh, ctxl);

    gemm3<0><<<gproj, 256, GEMM_SMEM>>>(ctxh, ctxl, Wh + 3*(size_t)NW, Wl + 3*(size_t)NW,
        bo, out, nullptr, BB*TT, CC, CC, 1.0f);
}